// round 17
// baseline (speedup 1.0000x reference)
#include <cuda_runtime.h>
#include <cstdint>
#include <cfloat>

// Problem constants (dataset-fixed; T derived at launch from in_sizes)
#define C_CL   8
#define E_EX   8
#define D_DIM  4096
#define NTOT   (C_CL * E_EX)   // 64 output slots
#define MAX_T  8192
#define NSPLIT 4               // D-dim splits (1024 dims per warp)
#define WBUF   8192            // per-warp dynamic smem: 2 bufs x 8 tok x 512B
#define DSMEM  (8 * WBUF)      // 64KB per block

// Scratch (no allocs allowed)
__device__ int g_cnt[C_CL];
__device__ int g_cluster[MAX_T];
__device__ int g_bucket[C_CL * MAX_T];
__device__ int g_order[MAX_T];

__global__ void zero_cnt_kernel() {
    if (threadIdx.x < C_CL) g_cnt[threadIdx.x] = 0;
}

// Read expert_ids[i] robustly whether delivered as int32 or int64.
__device__ __forceinline__ int read_eid(const void* p, int i) {
    const int* p32 = (const int*)p;
    if (__ldg(p32 + 1) == 0) return (int)__ldg(((const long long*)p) + i);
    return __ldg(p32 + i);
}

// ---- packed f32x2 helpers ----
__device__ __forceinline__ unsigned long long fma2(unsigned long long a,
                                                   unsigned long long b,
                                                   unsigned long long c) {
    unsigned long long d;
    asm("fma.rn.f32x2 %0, %1, %2, %3;" : "=l"(d) : "l"(a), "l"(b), "l"(c));
    return d;
}
__device__ __forceinline__ unsigned long long add2(unsigned long long a,
                                                   unsigned long long b) {
    unsigned long long d;
    asm("add.rn.f32x2 %0, %1, %2;" : "=l"(d) : "l"(a), "l"(b));
    return d;
}
__device__ __forceinline__ float sum2(unsigned long long v) {
    return __uint_as_float((unsigned)(v & 0xffffffffull)) +
           __uint_as_float((unsigned)(v >> 32));
}

// ---- cp.async (LDGSTS): zero-register deep x pipeline ----
__device__ __forceinline__ void cp16(unsigned dst, const void* src) {
    asm volatile("cp.async.cg.shared.global [%0], [%1], 16;"
                 :: "r"(dst), "l"(src) : "memory");
}
__device__ __forceinline__ void cp_commit() {
    asm volatile("cp.async.commit_group;" ::: "memory");
}
template <int N>
__device__ __forceinline__ void cp_wait() {
    asm volatile("cp.async.wait_group %0;" :: "n"(N) : "memory");
}

// ============================================================================
// Pass A: cluster logits + argmax + bucket scatter.
// Block = 8 warps = 2 token-groups(8 tokens) x 4 D-splits(1024 dims).
// x is staged per-warp via cp.async (double-buffered 128-dim chunks, no
// block barriers): x never touches the register-dependent path. Weights are
// batch-loaded (8 LDG) per iter; x read via conflict-free LDS.128.
// ============================================================================
__global__ void __launch_bounds__(256, 2) cluster_kernel(
    const float* __restrict__ x,
    const float* __restrict__ Wc)
{
    extern __shared__ char dynsm[];
    __shared__ float s_part[2][NSPLIT][8][8];   // [tgl][split][tok_local][c]

    const int w    = threadIdx.x >> 5;
    const int lane = threadIdx.x & 31;
    const int tgl  = w >> 2;            // token-group within block (0..1)
    const int s    = w & 3;             // D-split (0..3)
    const int sub  = lane & 7;          // 16B slice within 128B line
    const int tq   = lane >> 3;         // quad index (0..3)
    const int tbase = blockIdx.x * 16 + tgl * 8;
    const int base = s * 256;           // ulonglong2 offset of this split

    char* wbuf = dynsm + w * WBUF;
    const unsigned wbuf_u = (unsigned)__cvta_generic_to_shared(wbuf);

    // Stage chunk c (32 x 16B per token, 8 tokens) into buffer b.
    auto stage = [&](int c, int b) {
#pragma unroll
        for (int j = 0; j < 8; ++j) {
            const char* src = (const char*)(x + (size_t)(tbase + j) * D_DIM)
                            + (size_t)(base + c * 32 + lane) * 16;
            cp16(wbuf_u + b * 4096 + j * 512 + lane * 16, src);
        }
        cp_commit();
    };

    unsigned long long accA[C_CL], accB[C_CL];
#pragma unroll
    for (int c = 0; c < C_CL; ++c) { accA[c] = 0ull; accB[c] = 0ull; }

    stage(0, 0);
    stage(1, 1);

#pragma unroll
    for (int c = 0; c < 8; ++c) {
        if (c < 7) cp_wait<1>(); else cp_wait<0>();
        const int b = c & 1;
#pragma unroll
        for (int kk = 0; kk < 4; ++kk) {
            const int f4 = base + (c * 4 + kk) * 8 + sub;
            ulonglong2 xa = *reinterpret_cast<const ulonglong2*>(
                wbuf + b * 4096 + tq * 512 + (kk * 8 + sub) * 16);
            ulonglong2 xb = *reinterpret_cast<const ulonglong2*>(
                wbuf + b * 4096 + (4 + tq) * 512 + (kk * 8 + sub) * 16);
            ulonglong2 wv[C_CL];
#pragma unroll
            for (int cc = 0; cc < C_CL; ++cc)
                wv[cc] = reinterpret_cast<const ulonglong2*>(Wc + cc * D_DIM)[f4];
#pragma unroll
            for (int cc = 0; cc < C_CL; ++cc) {
                accA[cc] = fma2(xa.x, wv[cc].x, accA[cc]);
                accA[cc] = fma2(xa.y, wv[cc].y, accA[cc]);
                accB[cc] = fma2(xb.x, wv[cc].x, accB[cc]);
                accB[cc] = fma2(xb.y, wv[cc].y, accB[cc]);
            }
        }
        if (c + 2 < 8) stage(c + 2, b);
    }

    // Reduce across the 8 lanes of each quad.
#pragma unroll
    for (int d = 1; d <= 4; d <<= 1)
#pragma unroll
        for (int c = 0; c < C_CL; ++c) {
            accA[c] = add2(accA[c], __shfl_xor_sync(0xffffffffu, accA[c], d));
            accB[c] = add2(accB[c], __shfl_xor_sync(0xffffffffu, accB[c], d));
        }

#pragma unroll
    for (int c = 0; c < C_CL; ++c)
        if (sub == c) {
            s_part[tgl][s][tq][c]     = sum2(accA[c]);
            s_part[tgl][s][4 + tq][c] = sum2(accB[c]);
        }
    __syncthreads();

    // Combine splits + argmax: 128 threads = 2 tg x 8 tok x 8 c.
    if (threadIdx.x < 128) {
        const int tgl2 = threadIdx.x >> 6;
        const int tl   = (threadIdx.x >> 3) & 7;
        const int c    = threadIdx.x & 7;
        float v = s_part[tgl2][0][tl][c] + s_part[tgl2][1][tl][c]
                + s_part[tgl2][2][tl][c] + s_part[tgl2][3][tl][c];
        int bi = c;
#pragma unroll
        for (int d = 1; d <= 4; d <<= 1) {
            float vo = __shfl_xor_sync(0xffffffffu, v, d);
            int   io = __shfl_xor_sync(0xffffffffu, bi, d);
            if (vo > v || (vo == v && io < bi)) { v = vo; bi = io; }  // first-max
        }
        if (c == 0) {
            const int t = blockIdx.x * 16 + tgl2 * 8 + tl;
            g_cluster[t] = bi;
            int r = atomicAdd(&g_cnt[bi], 1);
            g_bucket[bi * MAX_T + r] = t;
        }
    }
}

// ============================================================================
// Middle: compact gapped buckets into cluster-major flat order (8 blocks),
// reversed within each bucket.
// ============================================================================
__global__ void __launch_bounds__(256) order_kernel() {
    const int c = blockIdx.x;
    int b = 0;
    for (int cc = 0; cc < c; ++cc) b += g_cnt[cc];
    const int n = g_cnt[c];
    for (int i = threadIdx.x; i < n; i += 256)
        g_order[b + i] = g_bucket[c * MAX_T + (n - 1 - i)];
}

// ============================================================================
// Pass B: expert logits + scatter. Same per-warp cp.async x pipeline; quads
// taken cluster-major from g_order (fast path shares weight registers).
// ============================================================================
__global__ void __launch_bounds__(256, 2) expert_kernel(
    const float* __restrict__ x,
    const float* __restrict__ We,
    const void* __restrict__ eids,
    float* __restrict__ out)
{
    extern __shared__ char dynsm[];
    __shared__ float s_part[2][NSPLIT][8][8];   // [tgl][split][tok_local][e]
    __shared__ float s_logit[16][8];
    __shared__ int   s_eid[16][8];
    __shared__ int   s_tok[16];
    __shared__ int   s_cl[16];

    const int w    = threadIdx.x >> 5;
    const int lane = threadIdx.x & 31;
    const int tgl  = w >> 2;
    const int s    = w & 3;
    const int sub  = lane & 7;
    const int tq   = lane >> 3;
    const int pbase = blockIdx.x * 16 + tgl * 8;
    const int base = s * 256;

    const int tokA = g_order[pbase + tq];
    const int tokB = g_order[pbase + 4 + tq];
    const int cA   = g_cluster[tokA];
    const int cB   = g_cluster[tokB];
    if (s == 0 && sub == 0) {
        s_tok[tgl * 8 + tq]     = tokA;  s_cl[tgl * 8 + tq]     = cA;
        s_tok[tgl * 8 + 4 + tq] = tokB;  s_cl[tgl * 8 + 4 + tq] = cB;
    }
    __syncthreads();   // s_tok visible to the staging loop below

    char* wbuf = dynsm + w * WBUF;
    const unsigned wbuf_u = (unsigned)__cvta_generic_to_shared(wbuf);

    auto stage = [&](int c, int b) {
#pragma unroll
        for (int j = 0; j < 8; ++j) {
            const int t = s_tok[tgl * 8 + j];
            const char* src = (const char*)(x + (size_t)t * D_DIM)
                            + (size_t)(base + c * 32 + lane) * 16;
            cp16(wbuf_u + b * 4096 + j * 512 + lane * 16, src);
        }
        cp_commit();
    };

    const float* wbA = We + (size_t)cA * (E_EX * D_DIM);
    const float* wbB = We + (size_t)cB * (E_EX * D_DIM);

    unsigned long long accA[E_EX], accB[E_EX];
#pragma unroll
    for (int e = 0; e < E_EX; ++e) { accA[e] = 0ull; accB[e] = 0ull; }

    stage(0, 0);
    stage(1, 1);

    if (__all_sync(0xffffffffu, cA == cB)) {
        // Fast path: one weight base for the whole warp; batched w loads.
#pragma unroll
        for (int c = 0; c < 8; ++c) {
            if (c < 7) cp_wait<1>(); else cp_wait<0>();
            const int b = c & 1;
#pragma unroll
            for (int kk = 0; kk < 4; ++kk) {
                const int f4 = base + (c * 4 + kk) * 8 + sub;
                ulonglong2 xa = *reinterpret_cast<const ulonglong2*>(
                    wbuf + b * 4096 + tq * 512 + (kk * 8 + sub) * 16);
                ulonglong2 xb = *reinterpret_cast<const ulonglong2*>(
                    wbuf + b * 4096 + (4 + tq) * 512 + (kk * 8 + sub) * 16);
                ulonglong2 wv[E_EX];
#pragma unroll
                for (int e = 0; e < E_EX; ++e)
                    wv[e] = reinterpret_cast<const ulonglong2*>(wbA + e * D_DIM)[f4];
#pragma unroll
                for (int e = 0; e < E_EX; ++e) {
                    accA[e] = fma2(xa.x, wv[e].x, accA[e]);
                    accA[e] = fma2(xa.y, wv[e].y, accA[e]);
                    accB[e] = fma2(xb.x, wv[e].x, accB[e]);
                    accB[e] = fma2(xb.y, wv[e].y, accB[e]);
                }
            }
            if (c + 2 < 8) stage(c + 2, b);
        }
    } else {
        // Slow path (rare boundary warps): per-quad weight loads, unbatched.
#pragma unroll
        for (int c = 0; c < 8; ++c) {
            if (c < 7) cp_wait<1>(); else cp_wait<0>();
            const int b = c & 1;
#pragma unroll
            for (int kk = 0; kk < 4; ++kk) {
                const int f4 = base + (c * 4 + kk) * 8 + sub;
                ulonglong2 xa = *reinterpret_cast<const ulonglong2*>(
                    wbuf + b * 4096 + tq * 512 + (kk * 8 + sub) * 16);
                ulonglong2 xb = *reinterpret_cast<const ulonglong2*>(
                    wbuf + b * 4096 + (4 + tq) * 512 + (kk * 8 + sub) * 16);
#pragma unroll
                for (int e = 0; e < E_EX; ++e) {
                    ulonglong2 wa = reinterpret_cast<const ulonglong2*>(wbA + e * D_DIM)[f4];
                    ulonglong2 wb2 = reinterpret_cast<const ulonglong2*>(wbB + e * D_DIM)[f4];
                    accA[e] = fma2(xa.x, wa.x, accA[e]);
                    accA[e] = fma2(xa.y, wa.y, accA[e]);
                    accB[e] = fma2(xb.x, wb2.x, accB[e]);
                    accB[e] = fma2(xb.y, wb2.y, accB[e]);
                }
            }
            if (c + 2 < 8) stage(c + 2, b);
        }
    }

#pragma unroll
    for (int d = 1; d <= 4; d <<= 1)
#pragma unroll
        for (int e = 0; e < E_EX; ++e) {
            accA[e] = add2(accA[e], __shfl_xor_sync(0xffffffffu, accA[e], d));
            accB[e] = add2(accB[e], __shfl_xor_sync(0xffffffffu, accB[e], d));
        }

#pragma unroll
    for (int e = 0; e < E_EX; ++e)
        if (sub == e) {
            s_part[tgl][s][tq][e]     = sum2(accA[e]);
            s_part[tgl][s][4 + tq][e] = sum2(accB[e]);
        }
    __syncthreads();

    // Combine splits + fetch expert ids: 128 threads = 16 tok x 8 e.
    if (threadIdx.x < 128) {
        const int tl2 = threadIdx.x >> 3;
        const int e   = threadIdx.x & 7;
        const int tgl2 = tl2 >> 3, tli = tl2 & 7;
        s_logit[tl2][e] = s_part[tgl2][0][tli][e] + s_part[tgl2][1][tli][e]
                        + s_part[tgl2][2][tli][e] + s_part[tgl2][3][tli][e];
        s_eid[tl2][e] = read_eid(eids, s_cl[tl2] * E_EX + e);
    }
    __syncthreads();

    // Scatter: 256 threads = 16 tokens x 16 float4 (full 64-col rows).
    {
        const int tl3 = threadIdx.x >> 4;
        const int q   = threadIdx.x & 15;
        const int tok3 = s_tok[tl3];
        float v[4];
#pragma unroll
        for (int j = 0; j < 4; ++j) {
            const int col = q * 4 + j;
            float val = -FLT_MAX;              // == jnp.finfo(float32).min
#pragma unroll
            for (int e = 0; e < E_EX; ++e)
                val = (s_eid[tl3][e] == col) ? s_logit[tl3][e] : val;
            v[j] = val;
        }
        reinterpret_cast<float4*>(out + (size_t)tok3 * NTOT)[q] =
            make_float4(v[0], v[1], v[2], v[3]);
    }
}

extern "C" void kernel_launch(void* const* d_in, const int* in_sizes, int n_in,
                              void* d_out, int out_size) {
    const float* x    = (const float*)d_in[0];
    const float* Wc   = (const float*)d_in[1];
    const float* We   = (const float*)d_in[2];
    const void*  eids = d_in[3];
    float*       out  = (float*)d_out;

    const int D = in_sizes[2] / in_sizes[3];     // 4096
    const int T = in_sizes[0] / D;               // 8192
    (void)n_in; (void)out_size;

    cudaFuncSetAttribute(cluster_kernel,
                         cudaFuncAttributeMaxDynamicSharedMemorySize, DSMEM);
    cudaFuncSetAttribute(expert_kernel,
                         cudaFuncAttributeMaxDynamicSharedMemorySize, DSMEM);

    zero_cnt_kernel<<<1, 32>>>();

    const int blocks = T / 16;           // 16 tokens per block
    cluster_kernel<<<blocks, 256, DSMEM>>>(x, Wc);
    order_kernel<<<C_CL, 256>>>();
    expert_kernel<<<blocks, 256, DSMEM>>>(x, We, eids, out);
}